// round 3
// baseline (speedup 1.0000x reference)
#include <cuda_runtime.h>
#include <math.h>

// Problem constants
#define B_   128
#define T_   2048
#define H_   512
#define K_   20      // per-branch input dim
#define HC   256     // channel pairs per block (thread c handles channels c and c+256)
#define NW   8       // warps per block
#define TILE 32      // timesteps staged in smem per refill

typedef unsigned long long ull;

// ---------------- device-global scratch (no allocations allowed) ----------------
// Folded, packed weights: g_W1[k][c] = ( s1[c]*W1[c][k] , s1[c+256]*W1[c+256][k] )
// where s1[h] = Wo[h]*(1-alpha[h])*(1-beta1[h]); similarly branch 2.
__device__ float2 g_W1[K_][HC];
__device__ float2 g_W2[K_][HC];
__device__ float2 g_B1[HC];   // (beta1[c], beta1[c+256])
__device__ float2 g_B2[HC];
__device__ float2 g_A [HC];   // alpha pairs
__device__ float2 g_b1[HC];   // folded biases s1*b1
__device__ float2 g_b2[HC];
__device__ float  g_ypart[B_ * NW * T_];   // per-warp partial sums, 8.4 MB

// ---------------- packed f32x2 helpers (sm_103a) ----------------
__device__ __forceinline__ void u2f(ull v, float& lo, float& hi) {
    asm("mov.b64 {%0,%1},%2;" : "=f"(lo), "=f"(hi) : "l"(v));
}
__device__ __forceinline__ ull fma2(ull a, ull b, ull c) {
    ull d; asm("fma.rn.f32x2 %0,%1,%2,%3;" : "=l"(d) : "l"(a), "l"(b), "l"(c)); return d;
}
__device__ __forceinline__ ull add2(ull a, ull b) {
    ull d; asm("add.rn.f32x2 %0,%1,%2;" : "=l"(d) : "l"(a), "l"(b)); return d;
}

// ---------------- kernel 0: fold & pack parameters ----------------
__global__ void prep_kernel(const float* __restrict__ W1, const float* __restrict__ b1,
                            const float* __restrict__ W2, const float* __restrict__ b2,
                            const float* __restrict__ Wo,
                            const float* __restrict__ tm, const float* __restrict__ tn1,
                            const float* __restrict__ tn2) {
    int h = threadIdx.x;            // 0..511
    if (h >= H_) return;
    float a   = 1.0f / (1.0f + expf(-tm[h]));
    float be1 = 1.0f / (1.0f + expf(-tn1[h]));
    float be2 = 1.0f / (1.0f + expf(-tn2[h]));
    float wo  = Wo[h];              // Wo is [1,512]
    float s1  = wo * (1.0f - a) * (1.0f - be1);
    float s2  = wo * (1.0f - a) * (1.0f - be2);

    int c  = h & (HC - 1);
    int hi = h >> 8;                // 0 -> .x, 1 -> .y
    for (int k = 0; k < K_; k++) {
        ((float*)&g_W1[k][c])[hi] = s1 * W1[h * K_ + k];
        ((float*)&g_W2[k][c])[hi] = s2 * W2[h * K_ + k];
    }
    ((float*)&g_B1[c])[hi] = be1;
    ((float*)&g_B2[c])[hi] = be2;
    ((float*)&g_A [c])[hi] = a;
    ((float*)&g_b1[c])[hi] = s1 * b1[h];
    ((float*)&g_b2[c])[hi] = s2 * b2[h];
}

// ---------------- kernel 1: fused projection + scan + warp partial reduce ----------------
__global__ void __launch_bounds__(HC) scan_kernel(const float* __restrict__ x) {
    __shared__ float2 XT[TILE][2 * K_];     // x values duplicated {v,v}; 10 KB

    const int b    = blockIdx.x;
    const int tid  = threadIdx.x;           // 0..255
    const int w    = tid >> 5;
    const int lane = tid & 31;

    // Load folded weights & params into registers (packed pairs)
    ull w1[K_], w2[K_];
#pragma unroll
    for (int k = 0; k < K_; k++) {
        w1[k] = *reinterpret_cast<const ull*>(&g_W1[k][tid]);
        w2[k] = *reinterpret_cast<const ull*>(&g_W2[k][tid]);
    }
    const ull B1  = *reinterpret_cast<const ull*>(&g_B1[tid]);
    const ull B2  = *reinterpret_cast<const ull*>(&g_B2[tid]);
    const ull A   = *reinterpret_cast<const ull*>(&g_A [tid]);
    const ull bb1 = *reinterpret_cast<const ull*>(&g_b1[tid]);
    const ull bb2 = *reinterpret_cast<const ull*>(&g_b2[tid]);

    ull D1 = 0ull, D2 = 0ull, M = 0ull;     // packed (0.0f, 0.0f)

    const float* xb = x + (size_t)b * T_ * (2 * K_);
    float* yp = g_ypart + (size_t)(b * NW + w) * T_;

#pragma unroll 1
    for (int t0 = 0; t0 < T_; t0 += TILE) {
        __syncthreads();
        // stage TILE timesteps of x, duplicated into both f32x2 lanes
        for (int i = tid; i < TILE * 2 * K_; i += HC) {
            float v = xb[t0 * 2 * K_ + i];
            ((float2*)XT)[i] = make_float2(v, v);
        }
        __syncthreads();

#pragma unroll 1
        for (int tq = 0; tq < TILE / 4; tq++) {
            float p[4];
#pragma unroll
            for (int u = 0; u < 4; u++) {
                const int tt = tq * 4 + u;
                ull a0 = bb1, a1 = 0ull, c0 = bb2, c1 = 0ull;
#pragma unroll
                for (int k = 0; k < K_; k += 2) {
                    a0 = fma2(w1[k],     *reinterpret_cast<const ull*>(&XT[tt][k]),          a0);
                    a1 = fma2(w1[k + 1], *reinterpret_cast<const ull*>(&XT[tt][k + 1]),      a1);
                }
#pragma unroll
                for (int k = 0; k < K_; k += 2) {
                    c0 = fma2(w2[k],     *reinterpret_cast<const ull*>(&XT[tt][K_ + k]),     c0);
                    c1 = fma2(w2[k + 1], *reinterpret_cast<const ull*>(&XT[tt][K_ + k + 1]), c1);
                }
                const ull i1 = add2(a0, a1);
                const ull i2 = add2(c0, c1);
                // D1 = beta1*D1 + s1*i1   (s1 folded into weights already)
                D1 = fma2(B1, D1, i1);
                D2 = fma2(B2, D2, i2);
                // M = alpha*M + (D1 + D2)
                M  = fma2(A, M, add2(D1, D2));
                float lo, hi; u2f(M, lo, hi);
                p[u] = lo + hi;
            }
            // warp-level reduction of 4 independent timestep partials
#pragma unroll
            for (int off = 16; off > 0; off >>= 1) {
#pragma unroll
                for (int u = 0; u < 4; u++)
                    p[u] += __shfl_down_sync(0xffffffffu, p[u], off);
            }
            if (lane == 0) {
                float4 o = make_float4(p[0], p[1], p[2], p[3]);
                *reinterpret_cast<float4*>(&yp[t0 + tq * 4]) = o;
            }
        }
    }
}

// ---------------- kernel 2: combine warp partials, bias, sigmoid ----------------
__global__ void finish_kernel(float* __restrict__ out, const float* __restrict__ bo) {
    int i = blockIdx.x * blockDim.x + threadIdx.x;
    if (i >= B_ * T_) return;
    int b = i >> 11;
    int t = i & (T_ - 1);
    float s = bo[0];
#pragma unroll
    for (int w = 0; w < NW; w++)
        s += g_ypart[(size_t)(b * NW + w) * T_ + t];
    out[i] = 1.0f / (1.0f + expf(-s));
}

// ---------------- launch ----------------
extern "C" void kernel_launch(void* const* d_in, const int* in_sizes, int n_in,
                              void* d_out, int out_size) {
    const float* x   = (const float*)d_in[0];
    const float* W1  = (const float*)d_in[1];
    const float* b1  = (const float*)d_in[2];
    const float* W2  = (const float*)d_in[3];
    const float* b2  = (const float*)d_in[4];
    const float* Wo  = (const float*)d_in[5];
    const float* bo  = (const float*)d_in[6];
    const float* tm  = (const float*)d_in[7];
    const float* tn1 = (const float*)d_in[8];
    const float* tn2 = (const float*)d_in[9];
    float* out = (float*)d_out;

    prep_kernel<<<1, H_>>>(W1, b1, W2, b2, Wo, tm, tn1, tn2);
    scan_kernel<<<B_, HC>>>(x);
    finish_kernel<<<(B_ * T_ + 255) / 256, 256>>>(out, bo);
}

// round 4
// speedup vs baseline: 1.0323x; 1.0323x over previous
#include <cuda_runtime.h>
#include <math.h>

#define B_   128
#define T_   2048
#define HF   1024     // half (chunk) length, C=2
#define K_   20
#define HC   256      // channel pairs
#define TILE 32

typedef unsigned long long ull;

// ---------------- device-global scratch ----------------
__device__ float g_y0[B_ * T_];            // pre-sigmoid partial sums, 1 MB
__device__ ull   g_stM [B_ * HC];          // chunk-0 end states (packed f32x2)
__device__ ull   g_stD1[B_ * HC];
__device__ ull   g_stD2[B_ * HC];

// ---------------- packed f32x2 helpers (sm_103a) ----------------
__device__ __forceinline__ ull fma2(ull a, ull b, ull c) {
    ull d; asm("fma.rn.f32x2 %0,%1,%2,%3;" : "=l"(d) : "l"(a), "l"(b), "l"(c)); return d;
}
__device__ __forceinline__ ull add2(ull a, ull b) {
    ull d; asm("add.rn.f32x2 %0,%1,%2;" : "=l"(d) : "l"(a), "l"(b)); return d;
}
__device__ __forceinline__ ull mul2(ull a, ull b) {
    ull d; asm("mul.rn.f32x2 %0,%1,%2;" : "=l"(d) : "l"(a), "l"(b)); return d;
}
__device__ __forceinline__ ull pack2(float lo, float hi) {
    ull d; asm("mov.b64 %0,{%1,%2};" : "=l"(d) : "f"(lo), "f"(hi)); return d;
}
__device__ __forceinline__ ull dup2(float v) {
    ull d; asm("mov.b64 %0,{%1,%1};" : "=l"(d) : "f"(v)); return d;
}
__device__ __forceinline__ void u2f(ull v, float& lo, float& hi) {
    asm("mov.b64 {%0,%1},%2;" : "=f"(lo), "=f"(hi) : "l"(v));
}
__device__ __forceinline__ float sigm(float v) { return 1.0f / (1.0f + expf(-v)); }

// ---------------- kernel 1: fused fold + projection + scan (per T-chunk) ----------------
__global__ void __launch_bounds__(256, 2) scanA_kernel(
    const float* __restrict__ x,
    const float* __restrict__ W1, const float* __restrict__ b1,
    const float* __restrict__ W2, const float* __restrict__ b2,
    const float* __restrict__ Wo,
    const float* __restrict__ tm, const float* __restrict__ tn1,
    const float* __restrict__ tn2)
{
    const int bx   = blockIdx.x;
    const int b    = bx >> 1;
    const int half = bx & 1;
    const int tid  = threadIdx.x;
    const int w    = tid >> 5;
    const int lane = tid & 31;

    // ---- fold parameters for this thread's channel pair (h0=tid, h1=tid+256) ----
    ull w1[K_], w2[K_], B1v, B2v, Av, bb1, bb2;
    {
        const int h0 = tid, h1 = tid + HC;
        float al0 = sigm(tm[h0]),  al1 = sigm(tm[h1]);
        float be10 = sigm(tn1[h0]), be11 = sigm(tn1[h1]);
        float be20 = sigm(tn2[h0]), be21 = sigm(tn2[h1]);
        float wo0 = Wo[h0], wo1 = Wo[h1];
        float s10 = wo0 * (1.0f - al0) * (1.0f - be10);
        float s11 = wo1 * (1.0f - al1) * (1.0f - be11);
        float s20 = wo0 * (1.0f - al0) * (1.0f - be20);
        float s21 = wo1 * (1.0f - al1) * (1.0f - be21);
#pragma unroll
        for (int k = 0; k < K_; k++) {
            w1[k] = pack2(s10 * W1[h0 * K_ + k], s11 * W1[h1 * K_ + k]);
            w2[k] = pack2(s20 * W2[h0 * K_ + k], s21 * W2[h1 * K_ + k]);
        }
        B1v = pack2(be10, be11);
        B2v = pack2(be20, be21);
        Av  = pack2(al0,  al1);
        bb1 = pack2(s10 * b1[h0], s11 * b1[h1]);
        bb2 = pack2(s20 * b2[h0], s21 * b2[h1]);
    }

    __shared__ ull   XT[TILE][2 * K_];   // x duplicated {v,v}; 10 KB
    __shared__ float ypW[8][TILE];       // per-warp per-t partials

    ull D1 = 0ull, D2 = 0ull, M = 0ull;

    const float* xb = x + ((size_t)b * T_ + (size_t)half * HF) * (2 * K_);
    float* y0 = g_y0 + (size_t)b * T_ + (size_t)half * HF;

#pragma unroll 1
    for (int tile = 0; tile < HF / TILE; tile++) {
        const int t0 = tile * TILE;
        __syncthreads();
        // drain previous tile's partials (warp 0) while all warps stage x
        if (tile > 0 && tid < TILE) {
            float s = 0.0f;
#pragma unroll
            for (int w8 = 0; w8 < 8; w8++) s += ypW[w8][tid];
            y0[t0 - TILE + tid] = s;
        }
        for (int i = tid; i < TILE * 2 * K_; i += 256) {
            float v = xb[(size_t)t0 * (2 * K_) + i];
            ((ull*)XT)[i] = dup2(v);
        }
        __syncthreads();

#pragma unroll 1
        for (int tq = 0; tq < TILE / 4; tq++) {
            float p[4];
#pragma unroll
            for (int u = 0; u < 4; u++) {
                const int tt = tq * 4 + u;
                ull a0 = bb1, a1 = 0ull, c0 = bb2, c1 = 0ull;
#pragma unroll
                for (int k = 0; k < K_; k += 4) {
                    ulonglong2 v0 = *reinterpret_cast<const ulonglong2*>(&XT[tt][k]);
                    ulonglong2 v1 = *reinterpret_cast<const ulonglong2*>(&XT[tt][k + 2]);
                    a0 = fma2(w1[k],     v0.x, a0);
                    a1 = fma2(w1[k + 1], v0.y, a1);
                    a0 = fma2(w1[k + 2], v1.x, a0);
                    a1 = fma2(w1[k + 3], v1.y, a1);
                }
#pragma unroll
                for (int k = 0; k < K_; k += 4) {
                    ulonglong2 v0 = *reinterpret_cast<const ulonglong2*>(&XT[tt][K_ + k]);
                    ulonglong2 v1 = *reinterpret_cast<const ulonglong2*>(&XT[tt][K_ + k + 2]);
                    c0 = fma2(w2[k],     v0.x, c0);
                    c1 = fma2(w2[k + 1], v0.y, c1);
                    c0 = fma2(w2[k + 2], v1.x, c0);
                    c1 = fma2(w2[k + 3], v1.y, c1);
                }
                D1 = fma2(B1v, D1, add2(a0, a1));
                D2 = fma2(B2v, D2, add2(c0, c1));
                M  = fma2(Av,  M,  add2(D1, D2));
                float lo, hi; u2f(M, lo, hi);
                p[u] = lo + hi;
            }
#pragma unroll
            for (int off = 16; off > 0; off >>= 1) {
#pragma unroll
                for (int u = 0; u < 4; u++)
                    p[u] += __shfl_down_sync(0xffffffffu, p[u], off);
            }
            if (lane == 0)
                *reinterpret_cast<float4*>(&ypW[w][tq * 4]) =
                    make_float4(p[0], p[1], p[2], p[3]);
        }
    }
    __syncthreads();
    if (tid < TILE) {
        float s = 0.0f;
#pragma unroll
        for (int w8 = 0; w8 < 8; w8++) s += ypW[w8][tid];
        y0[HF - TILE + tid] = s;
    }
    if (half == 0) {
        g_stM [b * HC + tid] = M;
        g_stD1[b * HC + tid] = D1;
        g_stD2[b * HC + tid] = D2;
    }
}

// stable S(d) = (a^{d+1} - bb^{d+1}) / (a - bb), given Ax=a^{d+1}, Bx=bb^{d+1}
__device__ __forceinline__ float seedS(float a, float bb, int d, float Ax, float Bx) {
    float diff = a - bb;
    if (fabsf(diff) > 0.04f * a) return (Ax - Bx) / diff;
    float lr  = log1pf((bb - a) / a);          // ln(bb/a), |lr| small
    float den = -expm1f(lr);
    float ad  = Ax / a;                         // a^d (0 if underflowed: benign)
    if (den == 0.0f) return (float)(d + 1) * ad;
    float num = -expm1f((float)(d + 1) * lr);
    return ad * (num / den);
}

// ---------------- kernel 2: cross-chunk correction + sigmoid for second half ----------------
__global__ void __launch_bounds__(256) corr_kernel(
    float* __restrict__ out, const float* __restrict__ bo,
    const float* __restrict__ tm, const float* __restrict__ tn1,
    const float* __restrict__ tn2)
{
    const int b    = blockIdx.x;           // 128 blocks
    const int w    = threadIdx.x >> 5;     // warp covers 128 deltas
    const int lane = threadIdx.x & 31;
    const int ds   = w * 128;

    ull A[8], P1[8], P2[8], G1[8], G2[8], M0[8], D10[8], D20[8];
    ull alp[8], b1p[8], b2p[8];

#pragma unroll
    for (int j = 0; j < 8; j++) {
        const int p = lane + 32 * j;
        float a_[2], be1_[2], be2_[2], Ax_[2], P1_[2], P2_[2], G1_[2], G2_[2];
#pragma unroll
        for (int hh = 0; hh < 2; hh++) {
            const int h = p + hh * HC;
            float a   = sigm(tm[h]);
            float be1 = sigm(tn1[h]);
            float be2 = sigm(tn2[h]);
            float la  = log2f(a), l1 = log2f(be1), l2 = log2f(be2);
            float Ax  = exp2f((float)(ds + 1) * la);
            float B1x = exp2f((float)(ds + 1) * l1);
            float B2x = exp2f((float)(ds + 1) * l2);
            a_[hh] = a; be1_[hh] = be1; be2_[hh] = be2;
            Ax_[hh] = Ax; P1_[hh] = B1x; P2_[hh] = B2x;
            G1_[hh] = be1 * seedS(a, be1, ds, Ax, B1x);
            G2_[hh] = be2 * seedS(a, be2, ds, Ax, B2x);
        }
        alp[j] = pack2(a_[0], a_[1]);
        b1p[j] = pack2(be1_[0], be1_[1]);
        b2p[j] = pack2(be2_[0], be2_[1]);
        A [j]  = pack2(Ax_[0], Ax_[1]);
        P1[j]  = pack2(P1_[0], P1_[1]);
        P2[j]  = pack2(P2_[0], P2_[1]);
        G1[j]  = pack2(G1_[0], G1_[1]);
        G2[j]  = pack2(G2_[0], G2_[1]);
        M0 [j] = g_stM [b * HC + p];
        D10[j] = g_stD1[b * HC + p];
        D20[j] = g_stD2[b * HC + p];
    }

    const float bov = bo[0];
    const float* y0h = g_y0 + (size_t)b * T_ + HF;

#pragma unroll 1
    for (int d = 0; d < 128; d++) {
        ull acc = 0ull;
#pragma unroll
        for (int j = 0; j < 8; j++) {
            acc = fma2(A [j], M0 [j], acc);
            acc = fma2(G1[j], D10[j], acc);
            acc = fma2(G2[j], D20[j], acc);
        }
#pragma unroll
        for (int j = 0; j < 8; j++) {
            A [j] = mul2(alp[j], A[j]);
            P1[j] = mul2(b1p[j], P1[j]);
            G1[j] = fma2(alp[j], G1[j], P1[j]);
            P2[j] = mul2(b2p[j], P2[j]);
            G2[j] = fma2(alp[j], G2[j], P2[j]);
        }
        float lo, hi; u2f(acc, lo, hi);
        float s = lo + hi;
#pragma unroll
        for (int off = 16; off > 0; off >>= 1)
            s += __shfl_xor_sync(0xffffffffu, s, off);
        if (lane == 0) {
            int t = ds + d;
            out[(size_t)b * T_ + HF + t] = 1.0f / (1.0f + expf(-(y0h[t] + s + bov)));
        }
    }
}

// ---------------- kernel 3: sigmoid for first half ----------------
__global__ void finish1_kernel(float* __restrict__ out, const float* __restrict__ bo) {
    int idx = blockIdx.x * blockDim.x + threadIdx.x;   // 0 .. B*HF
    if (idx >= B_ * HF) return;
    int b = idx >> 10;
    int t = idx & (HF - 1);
    out[(size_t)b * T_ + t] = 1.0f / (1.0f + expf(-(g_y0[(size_t)b * T_ + t] + bo[0])));
}

// ---------------- launch ----------------
extern "C" void kernel_launch(void* const* d_in, const int* in_sizes, int n_in,
                              void* d_out, int out_size) {
    const float* x   = (const float*)d_in[0];
    const float* W1  = (const float*)d_in[1];
    const float* b1  = (const float*)d_in[2];
    const float* W2  = (const float*)d_in[3];
    const float* b2  = (const float*)d_in[4];
    const float* Wo  = (const float*)d_in[5];
    const float* bo  = (const float*)d_in[6];
    const float* tm  = (const float*)d_in[7];
    const float* tn1 = (const float*)d_in[8];
    const float* tn2 = (const float*)d_in[9];
    float* out = (float*)d_out;

    scanA_kernel<<<B_ * 2, 256>>>(x, W1, b1, W2, b2, Wo, tm, tn1, tn2);
    corr_kernel<<<B_, 256>>>(out, bo, tm, tn1, tn2);
    finish1_kernel<<<(B_ * HF + 255) / 256, 256>>>(out, bo);
}

// round 5
// speedup vs baseline: 1.2558x; 1.2165x over previous
#include <cuda_runtime.h>
#include <math.h>

#define B_   128
#define T_   2048
#define HF   1024     // chunk length (C=2)
#define K_   20
#define HC   256      // channel pairs; thread tid owns channels 2*tid, 2*tid+1
#define TILE 32
#define NTILE (HF / TILE)

typedef unsigned long long ull;

// ---------------- device-global scratch ----------------
__device__ float g_y0[B_ * T_];            // pre-sigmoid sums (second half used)
__device__ ull   g_stM [B_ * HC];          // chunk-0 end states, packed (ch 2p, 2p+1)
__device__ ull   g_stD1[B_ * HC];
__device__ ull   g_stD2[B_ * HC];

// ---------------- packed f32x2 helpers (sm_103a) ----------------
__device__ __forceinline__ ull fma2(ull a, ull b, ull c) {
    ull d; asm("fma.rn.f32x2 %0,%1,%2,%3;" : "=l"(d) : "l"(a), "l"(b), "l"(c)); return d;
}
__device__ __forceinline__ ull add2(ull a, ull b) {
    ull d; asm("add.rn.f32x2 %0,%1,%2;" : "=l"(d) : "l"(a), "l"(b)); return d;
}
__device__ __forceinline__ ull mul2(ull a, ull b) {
    ull d; asm("mul.rn.f32x2 %0,%1,%2;" : "=l"(d) : "l"(a), "l"(b)); return d;
}
__device__ __forceinline__ ull pack2(float lo, float hi) {
    ull d; asm("mov.b64 %0,{%1,%2};" : "=l"(d) : "f"(lo), "f"(hi)); return d;
}
__device__ __forceinline__ float2 asf2(ull v) {
    float2 r; asm("mov.b64 {%0,%1},%2;" : "=f"(r.x), "=f"(r.y) : "l"(v)); return r;
}
__device__ __forceinline__ float sigm(float v) { return 1.0f / (1.0f + expf(-v)); }

// ---------------- kernel 1: fused fold + projection + scan (per T-chunk) ----------------
__global__ void __launch_bounds__(256, 2) scanA_kernel(
    const float* __restrict__ x, float* __restrict__ out,
    const float* __restrict__ W1, const float* __restrict__ b1,
    const float* __restrict__ W2, const float* __restrict__ b2,
    const float* __restrict__ Wo, const float* __restrict__ bo,
    const float* __restrict__ tm, const float* __restrict__ tn1,
    const float* __restrict__ tn2)
{
    const int bx   = blockIdx.x;
    const int b    = bx >> 1;
    const int half = bx & 1;
    const int tid  = threadIdx.x;
    const int w    = tid >> 5;
    const int lane = tid & 31;

    // ---- fold parameters; thread owns channels h0=2*tid, h1=2*tid+1 ----
    // f32x2 lanes now hold (k, k+1) pairs of ONE channel.
    ull w1a[K_ / 2], w1b[K_ / 2], w2a[K_ / 2], w2b[K_ / 2];
    ull B1v, B2v, Av;
    ull biasA1, biasB1, biasA2, biasB2;
    {
        const int h0 = 2 * tid, h1 = 2 * tid + 1;
        float al0 = sigm(tm[h0]),  al1 = sigm(tm[h1]);
        float be10 = sigm(tn1[h0]), be11 = sigm(tn1[h1]);
        float be20 = sigm(tn2[h0]), be21 = sigm(tn2[h1]);
        float wo0 = Wo[h0], wo1 = Wo[h1];
        float s10 = wo0 * (1.0f - al0) * (1.0f - be10);
        float s11 = wo1 * (1.0f - al1) * (1.0f - be11);
        float s20 = wo0 * (1.0f - al0) * (1.0f - be20);
        float s21 = wo1 * (1.0f - al1) * (1.0f - be21);
#pragma unroll
        for (int q = 0; q < K_ / 2; q++) {
            w1a[q] = pack2(s10 * W1[h0 * K_ + 2 * q], s10 * W1[h0 * K_ + 2 * q + 1]);
            w1b[q] = pack2(s11 * W1[h1 * K_ + 2 * q], s11 * W1[h1 * K_ + 2 * q + 1]);
            w2a[q] = pack2(s20 * W2[h0 * K_ + 2 * q], s20 * W2[h0 * K_ + 2 * q + 1]);
            w2b[q] = pack2(s21 * W2[h1 * K_ + 2 * q], s21 * W2[h1 * K_ + 2 * q + 1]);
        }
        B1v = pack2(be10, be11);
        B2v = pack2(be20, be21);
        Av  = pack2(al0,  al1);
        biasA1 = pack2(s10 * b1[h0], 0.0f);
        biasB1 = pack2(s11 * b1[h1], 0.0f);
        biasA2 = pack2(s20 * b2[h0], 0.0f);
        biasB2 = pack2(s21 * b2[h1], 0.0f);
    }

    __shared__ float XT[2][TILE][2 * K_];   // raw x, 2 buffers, 10 KB
    __shared__ float ypW[2][8][TILE];       // per-warp per-t partials, 2 buffers

    ull D1 = 0ull, D2 = 0ull, M = 0ull;

    const float* xb = x + ((size_t)b * T_ + (size_t)half * HF) * (2 * K_);
    float* y0 = g_y0 + (size_t)b * T_ + HF;             // only half==1 writes here
    float* ob = out + (size_t)b * T_;                    // only half==0 writes here
    const float bov = bo[0];

    // prologue: stage tile 0
    for (int i = tid; i < TILE * 2 * K_; i += 256)
        (&XT[0][0][0])[i] = xb[i];
    __syncthreads();

    int cur = 0;
#pragma unroll 1
    for (int tile = 0; tile < NTILE; tile++) {
        // issue global loads for next tile early (latency hidden by compute)
        float r[5];
        const bool hasNext = (tile + 1 < NTILE);
        if (hasNext) {
#pragma unroll
            for (int q = 0; q < 5; q++)
                r[q] = xb[(size_t)(tile + 1) * (TILE * 2 * K_) + tid + 256 * q];
        }

#pragma unroll 1
        for (int tq = 0; tq < TILE / 4; tq++) {
            float p[4];
#pragma unroll
            for (int u = 0; u < 4; u++) {
                const int tt = tq * 4 + u;
                ull A1 = biasA1, Bb1 = biasB1, A2 = biasA2, Bb2 = biasB2;
#pragma unroll
                for (int q = 0; q < 5; q++) {
                    ulonglong2 v = *reinterpret_cast<const ulonglong2*>(&XT[cur][tt][4 * q]);
                    A1  = fma2(w1a[2 * q],     v.x, A1);
                    Bb1 = fma2(w1b[2 * q],     v.x, Bb1);
                    A1  = fma2(w1a[2 * q + 1], v.y, A1);
                    Bb1 = fma2(w1b[2 * q + 1], v.y, Bb1);
                }
#pragma unroll
                for (int q = 0; q < 5; q++) {
                    ulonglong2 v = *reinterpret_cast<const ulonglong2*>(&XT[cur][tt][K_ + 4 * q]);
                    A2  = fma2(w2a[2 * q],     v.x, A2);
                    Bb2 = fma2(w2b[2 * q],     v.x, Bb2);
                    A2  = fma2(w2a[2 * q + 1], v.y, A2);
                    Bb2 = fma2(w2b[2 * q + 1], v.y, Bb2);
                }
                float2 fA1 = asf2(A1), fB1 = asf2(Bb1), fA2 = asf2(A2), fB2 = asf2(Bb2);
                ull i1 = pack2(fA1.x + fA1.y, fB1.x + fB1.y);
                ull i2 = pack2(fA2.x + fA2.y, fB2.x + fB2.y);
                D1 = fma2(B1v, D1, i1);
                D2 = fma2(B2v, D2, i2);
                M  = fma2(Av,  M,  add2(D1, D2));
                float2 fM = asf2(M);
                p[u] = fM.x + fM.y;
            }
#pragma unroll
            for (int off = 16; off > 0; off >>= 1) {
#pragma unroll
                for (int u = 0; u < 4; u++)
                    p[u] += __shfl_down_sync(0xffffffffu, p[u], off);
            }
            if (lane == 0)
                *reinterpret_cast<float4*>(&ypW[cur][w][tq * 4]) =
                    make_float4(p[0], p[1], p[2], p[3]);
        }

        // stage next tile into the other buffer
        if (hasNext) {
#pragma unroll
            for (int q = 0; q < 5; q++)
                (&XT[cur ^ 1][0][0])[tid + 256 * q] = r[q];
        }
        __syncthreads();

        // drain this tile's partials (warp 0) while others start next tile
        if (tid < TILE) {
            float s = 0.0f;
#pragma unroll
            for (int w8 = 0; w8 < 8; w8++) s += ypW[cur][w8][tid];
            const int t = tile * TILE + tid;
            if (half == 0) ob[t] = 1.0f / (1.0f + expf(-(s + bov)));
            else           y0[t] = s;
        }
        cur ^= 1;
    }

    if (half == 0) {
        g_stM [b * HC + tid] = M;
        g_stD1[b * HC + tid] = D1;
        g_stD2[b * HC + tid] = D2;
    }
}

// stable S(d) = (a^{d+1} - bb^{d+1}) / (a - bb), given Ax=a^{d+1}, Bx=bb^{d+1}
__device__ __forceinline__ float seedS(float a, float bb, int d, float Ax, float Bx) {
    float diff = a - bb;
    if (fabsf(diff) > 0.04f * a) return (Ax - Bx) / diff;
    float lr  = log1pf((bb - a) / a);
    float den = -expm1f(lr);
    float ad  = Ax / a;
    if (den == 0.0f) return (float)(d + 1) * ad;
    float num = -expm1f((float)(d + 1) * lr);
    return ad * (num / den);
}

// ---------------- kernel 2: cross-chunk correction + sigmoid for second half ----------------
__global__ void __launch_bounds__(256) corr_kernel(
    float* __restrict__ out, const float* __restrict__ bo,
    const float* __restrict__ tm, const float* __restrict__ tn1,
    const float* __restrict__ tn2)
{
    const int b    = blockIdx.x;
    const int w    = threadIdx.x >> 5;
    const int lane = threadIdx.x & 31;
    const int ds   = w * 128;

    ull A[8], P1[8], P2[8], G1[8], G2[8], M0[8], D10[8], D20[8];
    ull alp[8], b1p[8], b2p[8];

#pragma unroll
    for (int j = 0; j < 8; j++) {
        const int p = lane + 32 * j;           // channel-pair index: (2p, 2p+1)
        float a_[2], be1_[2], be2_[2], Ax_[2], P1_[2], P2_[2], G1_[2], G2_[2];
#pragma unroll
        for (int hh = 0; hh < 2; hh++) {
            const int h = 2 * p + hh;
            float a   = sigm(tm[h]);
            float be1 = sigm(tn1[h]);
            float be2 = sigm(tn2[h]);
            float la  = log2f(a), l1 = log2f(be1), l2 = log2f(be2);
            float Ax  = exp2f((float)(ds + 1) * la);
            float B1x = exp2f((float)(ds + 1) * l1);
            float B2x = exp2f((float)(ds + 1) * l2);
            a_[hh] = a; be1_[hh] = be1; be2_[hh] = be2;
            Ax_[hh] = Ax; P1_[hh] = B1x; P2_[hh] = B2x;
            G1_[hh] = be1 * seedS(a, be1, ds, Ax, B1x);
            G2_[hh] = be2 * seedS(a, be2, ds, Ax, B2x);
        }
        alp[j] = pack2(a_[0], a_[1]);
        b1p[j] = pack2(be1_[0], be1_[1]);
        b2p[j] = pack2(be2_[0], be2_[1]);
        A [j]  = pack2(Ax_[0], Ax_[1]);
        P1[j]  = pack2(P1_[0], P1_[1]);
        P2[j]  = pack2(P2_[0], P2_[1]);
        G1[j]  = pack2(G1_[0], G1_[1]);
        G2[j]  = pack2(G2_[0], G2_[1]);
        M0 [j] = g_stM [b * HC + p];
        D10[j] = g_stD1[b * HC + p];
        D20[j] = g_stD2[b * HC + p];
    }

    const float bov = bo[0];
    const float* y0h = g_y0 + (size_t)b * T_ + HF;

#pragma unroll 1
    for (int d = 0; d < 128; d++) {
        ull acc = 0ull;
#pragma unroll
        for (int j = 0; j < 8; j++) {
            acc = fma2(A [j], M0 [j], acc);
            acc = fma2(G1[j], D10[j], acc);
            acc = fma2(G2[j], D20[j], acc);
        }
#pragma unroll
        for (int j = 0; j < 8; j++) {
            A [j] = mul2(alp[j], A[j]);
            P1[j] = mul2(b1p[j], P1[j]);
            G1[j] = fma2(alp[j], G1[j], P1[j]);
            P2[j] = mul2(b2p[j], P2[j]);
            G2[j] = fma2(alp[j], G2[j], P2[j]);
        }
        float2 f = asf2(acc);
        float s = f.x + f.y;
#pragma unroll
        for (int off = 16; off > 0; off >>= 1)
            s += __shfl_xor_sync(0xffffffffu, s, off);
        if (lane == 0) {
            int t = ds + d;
            out[(size_t)b * T_ + HF + t] = 1.0f / (1.0f + expf(-(y0h[t] + s + bov)));
        }
    }
}

// ---------------- launch ----------------
extern "C" void kernel_launch(void* const* d_in, const int* in_sizes, int n_in,
                              void* d_out, int out_size) {
    const float* x   = (const float*)d_in[0];
    const float* W1  = (const float*)d_in[1];
    const float* b1  = (const float*)d_in[2];
    const float* W2  = (const float*)d_in[3];
    const float* b2  = (const float*)d_in[4];
    const float* Wo  = (const float*)d_in[5];
    const float* bo  = (const float*)d_in[6];
    const float* tm  = (const float*)d_in[7];
    const float* tn1 = (const float*)d_in[8];
    const float* tn2 = (const float*)d_in[9];
    float* out = (float*)d_out;

    scanA_kernel<<<B_ * 2, 256>>>(x, out, W1, b1, W2, b2, Wo, bo, tm, tn1, tn2);
    corr_kernel<<<B_, 256>>>(out, bo, tm, tn1, tn2);
}

// round 8
// speedup vs baseline: 1.6821x; 1.3395x over previous
#include <cuda_runtime.h>
#include <math.h>

#define B_    128
#define T_    2048
#define NC    8            // concurrent chunks
#define CL    256          // chunk length (T_/NC)
#define K_    20
#define H_    512
#define TILE  32
#define NT    (CL / TILE)  // 8 tiles per chunk

typedef unsigned long long ull;

// ---------------- device-global scratch ----------------
__device__ float g_ypA[B_ * T_];            // hgroup-0 partial y (reg space)
__device__ float g_ypB[B_ * T_];            // hgroup-1 partial y
__device__ float g_eM [B_ * 7 * H_];        // local end states per chunk 0..6
__device__ float g_eD1[B_ * 7 * H_];
__device__ float g_eD2[B_ * 7 * H_];
__device__ ull   g_sM [B_ * 7 * 256];       // true start states chunks 1..7, packed pairs
__device__ ull   g_sD1[B_ * 7 * 256];
__device__ ull   g_sD2[B_ * 7 * 256];

// ---------------- packed f32x2 helpers (sm_103a) ----------------
__device__ __forceinline__ ull fma2(ull a, ull b, ull c) {
    ull d; asm("fma.rn.f32x2 %0,%1,%2,%3;" : "=l"(d) : "l"(a), "l"(b), "l"(c)); return d;
}
__device__ __forceinline__ ull add2(ull a, ull b) {
    ull d; asm("add.rn.f32x2 %0,%1,%2;" : "=l"(d) : "l"(a), "l"(b)); return d;
}
__device__ __forceinline__ ull mul2(ull a, ull b) {
    ull d; asm("mul.rn.f32x2 %0,%1,%2;" : "=l"(d) : "l"(a), "l"(b)); return d;
}
__device__ __forceinline__ ull pack2(float lo, float hi) {
    ull d; asm("mov.b64 %0,{%1,%2};" : "=l"(d) : "f"(lo), "f"(hi)); return d;
}
__device__ __forceinline__ float2 asf2(ull v) {
    float2 r; asm("mov.b64 {%0,%1},%2;" : "=f"(r.x), "=f"(r.y) : "l"(v)); return r;
}
__device__ __forceinline__ float sigm(float v) { return 1.0f / (1.0f + expf(-v)); }

// ---------------- kernel 1: fused fold + projection + scan, one chunk, 1 ch/thread ----------------
__global__ void __launch_bounds__(256, 3) scan_kernel(
    const float* __restrict__ x,
    const float* __restrict__ W1, const float* __restrict__ b1,
    const float* __restrict__ W2, const float* __restrict__ b2,
    const float* __restrict__ Wo,
    const float* __restrict__ tm, const float* __restrict__ tn1,
    const float* __restrict__ tn2)
{
    const int bx   = blockIdx.x;                // b(7..4) | c(3..1) | g(0)
    const int b    = bx >> 4;
    const int c    = (bx >> 1) & 7;
    const int g    = bx & 1;
    const int tid  = threadIdx.x;
    const int w    = tid >> 5;
    const int lane = tid & 31;
    const int h    = g * 256 + tid;             // this thread's channel

    // ---- fold parameters for channel h ----
    float al  = sigm(tm[h]);
    float be1 = sigm(tn1[h]);
    float be2 = sigm(tn2[h]);
    float wo  = Wo[h];
    float s1  = wo * (1.0f - al) * (1.0f - be1);
    float s2  = wo * (1.0f - al) * (1.0f - be2);
    ull w1v[K_ / 2], w2v[K_ / 2];
#pragma unroll
    for (int q = 0; q < K_ / 2; q++) {
        w1v[q] = pack2(s1 * W1[h * K_ + 2 * q], s1 * W1[h * K_ + 2 * q + 1]);
        w2v[q] = pack2(s2 * W2[h * K_ + 2 * q], s2 * W2[h * K_ + 2 * q + 1]);
    }
    const ull biasA = pack2(s1 * b1[h], 0.0f);
    const ull biasC = pack2(s2 * b2[h], 0.0f);

    __shared__ __align__(16) float XT[2][TILE][2 * K_];   // raw x, double-buffered
    __shared__ float ypW[2][8][TILE];

    float D1 = 0.0f, D2 = 0.0f, M = 0.0f;

    const float* xb = x + ((size_t)b * T_ + (size_t)c * CL) * (2 * K_);
    float* yp = (g ? g_ypB : g_ypA) + (size_t)b * T_ + (size_t)c * CL;

    // prologue: stage tile 0
    for (int i = tid; i < TILE * 2 * K_; i += 256)
        (&XT[0][0][0])[i] = xb[i];
    __syncthreads();

    int cur = 0;
#pragma unroll 1
    for (int tile = 0; tile < NT; tile++) {
        float r[5];
        const bool hasNext = (tile + 1 < NT);
        if (hasNext) {
#pragma unroll
            for (int q = 0; q < 5; q++)
                r[q] = xb[(size_t)(tile + 1) * (TILE * 2 * K_) + tid + 256 * q];
        }

#pragma unroll 1
        for (int tq = 0; tq < TILE / 4; tq++) {
            float p[4];
#pragma unroll
            for (int u = 0; u < 4; u++) {
                const int tt = tq * 4 + u;
                ull Aa = biasA, Ab = 0ull, Ca = biasC, Cb = 0ull;
#pragma unroll
                for (int q = 0; q < 5; q++) {
                    ulonglong2 v = *reinterpret_cast<const ulonglong2*>(&XT[cur][tt][4 * q]);
                    Aa = fma2(w1v[2 * q],     v.x, Aa);
                    Ab = fma2(w1v[2 * q + 1], v.y, Ab);
                }
#pragma unroll
                for (int q = 0; q < 5; q++) {
                    ulonglong2 v = *reinterpret_cast<const ulonglong2*>(&XT[cur][tt][K_ + 4 * q]);
                    Ca = fma2(w2v[2 * q],     v.x, Ca);
                    Cb = fma2(w2v[2 * q + 1], v.y, Cb);
                }
                float2 f1 = asf2(add2(Aa, Ab));
                float2 f2 = asf2(add2(Ca, Cb));
                D1 = fmaf(be1, D1, f1.x + f1.y);
                D2 = fmaf(be2, D2, f2.x + f2.y);
                M  = fmaf(al,  M,  D1 + D2);
                p[u] = M;
            }
#pragma unroll
            for (int off = 16; off > 0; off >>= 1) {
#pragma unroll
                for (int u = 0; u < 4; u++)
                    p[u] += __shfl_down_sync(0xffffffffu, p[u], off);
            }
            if (lane == 0)
                *reinterpret_cast<float4*>(&ypW[cur][w][tq * 4]) =
                    make_float4(p[0], p[1], p[2], p[3]);
        }

        if (hasNext) {
#pragma unroll
            for (int q = 0; q < 5; q++)
                (&XT[cur ^ 1][0][0])[tid + 256 * q] = r[q];
        }
        __syncthreads();

        if (tid < TILE) {
            float s = 0.0f;
#pragma unroll
            for (int w8 = 0; w8 < 8; w8++) s += ypW[cur][w8][tid];
            yp[tile * TILE + tid] = s;
        }
        cur ^= 1;
    }

    if (c < 7) {
        const size_t si = ((size_t)b * 7 + c) * H_ + h;
        g_eM [si] = M;
        g_eD1[si] = D1;
        g_eD2[si] = D2;
    }
}

// stable S = (a^{d+1} - bb^{d+1})/(a - bb) given Ax=a^{d+1}, Bx=bb^{d+1}
__device__ __forceinline__ float seedS(float a, float bb, int d, float Ax, float Bx) {
    float diff = a - bb;
    if (fabsf(diff) > 0.04f * a) return (Ax - Bx) / diff;
    float lr  = log1pf((bb - a) / a);
    float den = -expm1f(lr);
    float ad  = Ax / a;
    if (den == 0.0f) return (float)(d + 1) * ad;
    float num = -expm1f((float)(d + 1) * lr);
    return ad * (num / den);
}

// ---------------- kernel 2: propagate true start states across chunks ----------------
__global__ void __launch_bounds__(256) combine_kernel(
    const float* __restrict__ tm, const float* __restrict__ tn1,
    const float* __restrict__ tn2)
{
    const int b = blockIdx.x;      // 128
    const int p = threadIdx.x;     // pair index: channels 2p, 2p+1

    float sM[2]  = {0.f, 0.f}, sD1[2] = {0.f, 0.f}, sD2[2] = {0.f, 0.f};
    float aL[2], b1L[2], b2L[2], G1L[2], G2L[2];
#pragma unroll
    for (int hh = 0; hh < 2; hh++) {
        const int h = 2 * p + hh;
        float al  = sigm(tm[h]);
        float be1 = sigm(tn1[h]);
        float be2 = sigm(tn2[h]);
        float la = log2f(al), l1 = log2f(be1), l2 = log2f(be2);
        aL[hh]  = exp2f(256.0f * la);
        b1L[hh] = exp2f(256.0f * l1);
        b2L[hh] = exp2f(256.0f * l2);
        G1L[hh] = be1 * seedS(al, be1, 255, aL[hh], b1L[hh]);
        G2L[hh] = be2 * seedS(al, be2, 255, aL[hh], b2L[hh]);
    }

#pragma unroll
    for (int c = 0; c < 7; c++) {
        const size_t ei = ((size_t)b * 7 + c) * H_ + 2 * p;
#pragma unroll
        for (int hh = 0; hh < 2; hh++) {
            float eM  = g_eM [ei + hh];
            float eD1 = g_eD1[ei + hh];
            float eD2 = g_eD2[ei + hh];
            float nM  = aL[hh] * sM[hh] + G1L[hh] * sD1[hh] + G2L[hh] * sD2[hh] + eM;
            float nD1 = b1L[hh] * sD1[hh] + eD1;
            float nD2 = b2L[hh] * sD2[hh] + eD2;
            sM[hh] = nM; sD1[hh] = nD1; sD2[hh] = nD2;
        }
        const size_t si = ((size_t)b * 7 + c) * 256 + p;
        g_sM [si] = pack2(sM[0],  sM[1]);
        g_sD1[si] = pack2(sD1[0], sD1[1]);
        g_sD2[si] = pack2(sD2[0], sD2[1]);
    }
}

// ---------------- kernel 3: homogeneous correction + sigmoid for chunks 1..7 ----------------
__global__ void __launch_bounds__(256) corr_kernel(
    float* __restrict__ out, const float* __restrict__ bo,
    const float* __restrict__ tm, const float* __restrict__ tn1,
    const float* __restrict__ tn2)
{
    const int b    = blockIdx.x / 7;
    const int c    = blockIdx.x % 7;           // correcting chunk c+1
    const int tid  = threadIdx.x;
    const int w    = tid >> 5;
    const int lane = tid & 31;
    const int p    = tid;                      // pair: channels 2p, 2p+1

    // coefficient seeds at delta=0: A=alpha, P=beta, G=beta (exactly)
    float al0  = sigm(tm[2 * p]),  al1  = sigm(tm[2 * p + 1]);
    float be10 = sigm(tn1[2 * p]), be11 = sigm(tn1[2 * p + 1]);
    float be20 = sigm(tn2[2 * p]), be21 = sigm(tn2[2 * p + 1]);
    ull alp = pack2(al0, al1);
    ull b1p = pack2(be10, be11);
    ull b2p = pack2(be20, be21);
    ull A  = alp, P1 = b1p, G1 = b1p, P2 = b2p, G2 = b2p;

    const size_t si = ((size_t)b * 7 + c) * 256 + p;
    const ull M0  = g_sM [si];
    const ull D10 = g_sD1[si];
    const ull D20 = g_sD2[si];

    __shared__ float part[8][CL];

#pragma unroll 1
    for (int d = 0; d < CL; d++) {
        ull acc = fma2(A, M0, fma2(G1, D10, mul2(G2, D20)));
        A  = mul2(alp, A);
        P1 = mul2(b1p, P1);
        G1 = fma2(alp, G1, P1);
        P2 = mul2(b2p, P2);
        G2 = fma2(alp, G2, P2);
        float2 f = asf2(acc);
        float s = f.x + f.y;
#pragma unroll
        for (int off = 16; off > 0; off >>= 1)
            s += __shfl_down_sync(0xffffffffu, s, off);
        if (lane == 0) part[w][d] = s;
    }
    __syncthreads();

    // combine 8 warp partials + base y + bias, sigmoid
    {
        const int t = (c + 1) * CL + tid;
        float s = bo[0];
#pragma unroll
        for (int w8 = 0; w8 < 8; w8++) s += part[w8][tid];
        s += g_ypA[(size_t)b * T_ + t] + g_ypB[(size_t)b * T_ + t];
        out[(size_t)b * T_ + t] = 1.0f / (1.0f + expf(-s));
    }
}

// ---------------- kernel 4: sigmoid for chunk 0 ----------------
__global__ void finish_kernel(float* __restrict__ out, const float* __restrict__ bo) {
    int i = blockIdx.x * blockDim.x + threadIdx.x;   // 0 .. B*CL
    if (i >= B_ * CL) return;
    int b = i >> 8;
    int t = i & (CL - 1);
    size_t idx = (size_t)b * T_ + t;
    out[idx] = 1.0f / (1.0f + expf(-(g_ypA[idx] + g_ypB[idx] + bo[0])));
}

// ---------------- launch ----------------
extern "C" void kernel_launch(void* const* d_in, const int* in_sizes, int n_in,
                              void* d_out, int out_size) {
    const float* x   = (const float*)d_in[0];
    const float* W1  = (const float*)d_in[1];
    const float* b1  = (const float*)d_in[2];
    const float* W2  = (const float*)d_in[3];
    const float* b2  = (const float*)d_in[4];
    const float* Wo  = (const float*)d_in[5];
    const float* bo  = (const float*)d_in[6];
    const float* tm  = (const float*)d_in[7];
    const float* tn1 = (const float*)d_in[8];
    const float* tn2 = (const float*)d_in[9];
    float* out = (float*)d_out;

    scan_kernel<<<B_ * NC * 2, 256>>>(x, W1, b1, W2, b2, Wo, tm, tn1, tn2);
    combine_kernel<<<B_, 256>>>(tm, tn1, tn2);
    corr_kernel<<<B_ * 7, 256>>>(out, bo, tm, tn1, tn2);
    finish_kernel<<<(B_ * CL + 255) / 256, 256>>>(out, bo);
}